// round 8
// baseline (speedup 1.0000x reference)
#include <cuda_runtime.h>
#include <cuda_fp16.h>
#include <cstdint>

#define IN_F   4096
#define OUT_F  11008
#define GS     128
#define MROWS  8192

// ---- scratch (device globals: allowed; no allocation APIs) ----
__device__ __half g_xh[(size_t)MROWS * IN_F];   // x in fp16,  67 MB
__device__ __half g_wt[(size_t)OUT_F * IN_F];   // W dequant fp16 [n][k], 90 MB

// =============================== prepass ===================================
__global__ __launch_bounds__(256)
void conv_x_kernel(const float* __restrict__ x)
{
    const size_t i = ((size_t)blockIdx.x * 256 + threadIdx.x) * 8;
    const float4 a = *reinterpret_cast<const float4*>(&x[i]);
    const float4 b = *reinterpret_cast<const float4*>(&x[i + 4]);
    __half2 h0 = __floats2half2_rn(a.x, a.y);
    __half2 h1 = __floats2half2_rn(a.z, a.w);
    __half2 h2 = __floats2half2_rn(b.x, b.y);
    __half2 h3 = __floats2half2_rn(b.z, b.w);
    uint4 u;
    u.x = reinterpret_cast<uint32_t&>(h0);
    u.y = reinterpret_cast<uint32_t&>(h1);
    u.z = reinterpret_cast<uint32_t&>(h2);
    u.w = reinterpret_cast<uint32_t&>(h3);
    *reinterpret_cast<uint4*>(&g_xh[i]) = u;
}

__global__ __launch_bounds__(256)
void dequant_w_kernel(const int* __restrict__ qweight,
                      const int* __restrict__ qzeros,
                      const float* __restrict__ scales)
{
    const int idx = blockIdx.x * 256 + threadIdx.x;   // one packed int32 each
    const int kk = idx / OUT_F;                       // packed k row (8 k's)
    const int n  = idx % OUT_F;
    const int g  = kk >> 4;                           // kk*8 / 128
    const unsigned q = (unsigned)qweight[idx];
    const int z = ((qzeros[(size_t)g * (OUT_F / 8) + (n >> 3)] >> ((n & 7) * 4)) & 0xF) + 1;
    const float s = scales[(size_t)g * OUT_F + n];
    __half h[8];
    #pragma unroll
    for (int j = 0; j < 8; ++j)
        h[j] = __float2half_rn((float)((int)((q >> (4 * j)) & 0xF) - z) * s);
    *reinterpret_cast<uint4*>(&g_wt[(size_t)n * IN_F + kk * 8]) =
        *reinterpret_cast<uint4*>(h);
}

// =============================== GEMM ======================================
constexpr int BM = 256;
constexpr int BN = 128;
constexpr int BK = 32;
constexpr int KPAD = 40;               // 80B row stride, conflict-free ldmatrix
constexpr int THREADS = 256;
constexpr int NC = IN_F / BK;          // 128
constexpr int STAGES = 3;

constexpr int A_HALFS = BM * KPAD;     // 10240
constexpr int B_HALFS = BN * KPAD;     // 5120
constexpr int ST_BYTES = (A_HALFS + B_HALFS) * 2;       // 30720
constexpr int SMEM_TOTAL = STAGES * ST_BYTES;           // 92160

__device__ __forceinline__ void cpasync16(uint32_t dst, const void* src) {
    asm volatile("cp.async.cg.shared.global [%0], [%1], 16;" :: "r"(dst), "l"(src));
}
__device__ __forceinline__ void cp_commit() {
    asm volatile("cp.async.commit_group;" ::: "memory");
}
__device__ __forceinline__ void cp_wait1() {
    asm volatile("cp.async.wait_group 1;" ::: "memory");
}

__device__ __forceinline__ void ldm_x4(uint32_t& r0, uint32_t& r1,
                                       uint32_t& r2, uint32_t& r3, uint32_t addr) {
    asm volatile("ldmatrix.sync.aligned.m8n8.x4.shared.b16 {%0,%1,%2,%3}, [%4];"
                 : "=r"(r0), "=r"(r1), "=r"(r2), "=r"(r3) : "r"(addr));
}

__device__ __forceinline__ void mma16816(float* d, const uint32_t* a, const uint32_t* b) {
    asm volatile("mma.sync.aligned.m16n8k16.row.col.f32.f16.f16.f32 "
                 "{%0,%1,%2,%3}, {%4,%5,%6,%7}, {%8,%9}, {%0,%1,%2,%3};"
                 : "+f"(d[0]), "+f"(d[1]), "+f"(d[2]), "+f"(d[3])
                 : "r"(a[0]), "r"(a[1]), "r"(a[2]), "r"(a[3]),
                   "r"(b[0]), "r"(b[1]));
}

__global__ __launch_bounds__(THREADS, 1)
void gemm_fp16_kernel(float* __restrict__ out)
{
    extern __shared__ __align__(16) char smem[];
    const uint32_t sb = (uint32_t)__cvta_generic_to_shared(smem);

    const int tid = threadIdx.x;
    const int lid = tid & 31;
    const int wid = tid >> 5;
    const int wm  = wid & 3;           // 4 warps along M (64 rows each)
    const int wn  = wid >> 2;          // 2 warps along N (64 cols each)
    const int m0  = blockIdx.y * BM;
    const int n0  = blockIdx.x * BN;

    const __half* xh = g_xh;
    const __half* wt = g_wt;

    float acc[4][8][4];
    #pragma unroll
    for (int i = 0; i < 4; ++i)
        #pragma unroll
        for (int j = 0; j < 8; ++j)
            #pragma unroll
            for (int q = 0; q < 4; ++q) acc[i][j][q] = 0.0f;

    auto issue = [&](int kt) {
        const int st = kt % STAGES;
        const uint32_t aD = sb + st * ST_BYTES;
        const uint32_t bD = aD + A_HALFS * 2;
        const int k0 = kt * BK;
        // A: 256 rows x 4 groups of 8 halfs = 1024 ops, 4/thread
        #pragma unroll
        for (int i = 0; i < 4; ++i) {
            const int task = i * 256 + tid;
            const int row = task >> 2, grp = task & 3;
            cpasync16(aD + (uint32_t)(row * KPAD + grp * 8) * 2,
                      &xh[(size_t)(m0 + row) * IN_F + k0 + grp * 8]);
        }
        // B: 128 rows x 4 groups = 512 ops, 2/thread
        #pragma unroll
        for (int i = 0; i < 2; ++i) {
            const int task = i * 256 + tid;
            const int row = task >> 2, grp = task & 3;
            cpasync16(bD + (uint32_t)(row * KPAD + grp * 8) * 2,
                      &wt[(size_t)(n0 + row) * IN_F + k0 + grp * 8]);
        }
        cp_commit();
    };

    auto compute = [&](int st) {
        const uint32_t aS = sb + st * ST_BYTES;
        const uint32_t bS = aS + A_HALFS * 2;
        #pragma unroll
        for (int ks = 0; ks < 2; ++ks) {
            uint32_t af[4][4];
            #pragma unroll
            for (int ma = 0; ma < 4; ++ma) {
                const int row = wm * 64 + ma * 16 + (lid & 15);
                const int col = ks * 16 + (lid >> 4) * 8;
                ldm_x4(af[ma][0], af[ma][1], af[ma][2], af[ma][3],
                       aS + (uint32_t)(row * KPAD + col) * 2);
            }
            uint32_t bf[8][2];
            #pragma unroll
            for (int g4 = 0; g4 < 4; ++g4) {
                const int row = wn * 64 + g4 * 16 + ((lid >> 4) & 1) * 8 + (lid & 7);
                const int col = ks * 16 + ((lid >> 3) & 1) * 8;
                uint32_t r0, r1, r2, r3;
                ldm_x4(r0, r1, r2, r3, bS + (uint32_t)(row * KPAD + col) * 2);
                bf[g4 * 2 + 0][0] = r0; bf[g4 * 2 + 0][1] = r1;
                bf[g4 * 2 + 1][0] = r2; bf[g4 * 2 + 1][1] = r3;
            }
            #pragma unroll
            for (int ma = 0; ma < 4; ++ma)
                #pragma unroll
                for (int na = 0; na < 8; ++na)
                    mma16816(acc[ma][na], af[ma], bf[na]);
        }
    };

    issue(0);
    issue(1);

    for (int kt = 0; kt < NC; ++kt) {
        cp_wait1();
        __syncthreads();
        if (kt + 2 < NC) issue(kt + 2);   // overwrites stage consumed 2 iters ago
        compute(kt % STAGES);
    }

    // ---- epilogue ----
    #pragma unroll
    for (int ma = 0; ma < 4; ++ma) {
        const int row = m0 + wm * 64 + ma * 16 + (lid >> 2);
        #pragma unroll
        for (int na = 0; na < 8; ++na) {
            const int col = n0 + wn * 64 + na * 8 + (lid & 3) * 2;
            float2 v01, v23;
            v01.x = acc[ma][na][0]; v01.y = acc[ma][na][1];
            v23.x = acc[ma][na][2]; v23.y = acc[ma][na][3];
            *reinterpret_cast<float2*>(&out[(size_t)row * OUT_F + col]) = v01;
            *reinterpret_cast<float2*>(&out[(size_t)(row + 8) * OUT_F + col]) = v23;
        }
    }
}

// =============================== launch ====================================
extern "C" void kernel_launch(void* const* d_in, const int* in_sizes, int n_in,
                              void* d_out, int out_size)
{
    const float* x       = (const float*)d_in[0];
    const int*   qweight = (const int*)  d_in[1];
    const int*   qzeros  = (const int*)  d_in[2];
    const float* scales  = (const float*)d_in[3];
    float*       out     = (float*)d_out;

    cudaFuncSetAttribute(gemm_fp16_kernel,
                         cudaFuncAttributeMaxDynamicSharedMemorySize, SMEM_TOTAL);

    conv_x_kernel<<<(MROWS * IN_F) / (256 * 8), 256>>>(x);
    dequant_w_kernel<<<(IN_F / 8) * OUT_F / 256, 256>>>(qweight, qzeros, scales);

    dim3 grid(OUT_F / BN, MROWS / BM);   // 86 x 32
    gemm_fp16_kernel<<<grid, THREADS, SMEM_TOTAL>>>(out);
}

// round 9
// speedup vs baseline: 1.2368x; 1.2368x over previous
#include <cuda_runtime.h>
#include <cuda_fp16.h>
#include <cstdint>

#define IN_F   4096
#define OUT_F  11008
#define GS     128
#define MROWS  8192

constexpr int BM = 128;
constexpr int BN = 256;
constexpr int BK = 32;               // k per chunk (fp16 elements)
constexpr int KPAD = 40;             // padded k stride (80B) -> conflict-free ldmatrix
constexpr int THREADS = 256;
constexpr int NC = IN_F / BK;        // 128 chunks

// dynamic smem layout (halfs): A[2][BM][KPAD] then B[2][BN][KPAD]
constexpr int A_STG_B = BM * KPAD * 2;            // 10240 bytes/stage
constexpr int B_STG_B = BN * KPAD * 2;            // 20480 bytes/stage
constexpr int B_BASE  = 2 * A_STG_B;              // 20480
constexpr int SMEM_TOTAL = 2 * A_STG_B + 2 * B_STG_B;   // 61440

__device__ __forceinline__ uint32_t f22h2(float a, float b) {
    __half2 h = __floats2half2_rn(a, b);
    return reinterpret_cast<uint32_t&>(h);
}

__device__ __forceinline__ void ldm_x4(uint32_t& r0, uint32_t& r1,
                                       uint32_t& r2, uint32_t& r3, uint32_t addr) {
    asm volatile("ldmatrix.sync.aligned.m8n8.x4.shared.b16 {%0,%1,%2,%3}, [%4];"
                 : "=r"(r0), "=r"(r1), "=r"(r2), "=r"(r3) : "r"(addr));
}

__device__ __forceinline__ void mma16816(float* d, const uint32_t* a, const uint32_t* b) {
    asm volatile("mma.sync.aligned.m16n8k16.row.col.f32.f16.f16.f32 "
                 "{%0,%1,%2,%3}, {%4,%5,%6,%7}, {%8,%9}, {%0,%1,%2,%3};"
                 : "+f"(d[0]), "+f"(d[1]), "+f"(d[2]), "+f"(d[3])
                 : "r"(a[0]), "r"(a[1]), "r"(a[2]), "r"(a[3]),
                   "r"(b[0]), "r"(b[1]));
}

__global__ __launch_bounds__(THREADS, 1)
void gptq_mma_kernel(const float* __restrict__ x,
                     const int*   __restrict__ qweight,
                     const int*   __restrict__ qzeros,
                     const float* __restrict__ scales,
                     float*       __restrict__ out)
{
    // k within each 8-group is stored permuted: pos(j) = (j&3)*2 + (j>>2),
    // applied identically to A and B (dot-product invariant).
    extern __shared__ __align__(16) char smem[];
    const uint32_t sb = (uint32_t)__cvta_generic_to_shared(smem);

    const int tid = threadIdx.x;
    const int lid = tid & 31;
    const int wid = tid >> 5;
    const int wm  = wid & 1;           // 2 warps along M (64 rows each)
    const int wn  = wid >> 1;          // 4 warps along N (64 cols each)
    const int m0  = blockIdx.y * BM;
    const int n0  = blockIdx.x * BN;

    // ---- producer thread mappings ----
    // A: 128 rows x 4 k-groups = 512 tasks, 2/thread.
    // B: 4 packed rows x 256 cols = 1024 int32, 4/thread (one column each).
    const int oc   = tid;              // 0..255 : output column within tile
    const int ncol = n0 + oc;
    const int zsh  = (oc & 7) * 4;

    float4 xr[4];
    int    wq[4];
    int    zw;
    float  sc;

    float acc[4][8][4];
    #pragma unroll
    for (int i = 0; i < 4; ++i)
        #pragma unroll
        for (int j = 0; j < 8; ++j)
            #pragma unroll
            for (int q = 0; q < 4; ++q) acc[i][j][q] = 0.0f;

    auto load_regs = [&](int kt) {
        const int k0 = kt * BK;
        #pragma unroll
        for (int i = 0; i < 2; ++i) {
            const int task = i * 256 + tid;
            const int row = task >> 2, grp = task & 3;
            const float* p = &x[(size_t)(m0 + row) * IN_F + k0 + grp * 8];
            xr[i * 2 + 0] = *reinterpret_cast<const float4*>(p);
            xr[i * 2 + 1] = *reinterpret_cast<const float4*>(p + 4);
        }
        const int g = k0 / GS;
        zw = qzeros[(size_t)g * (OUT_F / 8) + (ncol >> 3)];
        sc = scales[(size_t)g * OUT_F + ncol];
        #pragma unroll
        for (int r8 = 0; r8 < 4; ++r8)
            wq[r8] = qweight[(size_t)(k0 / 8 + r8) * OUT_F + ncol];
    };

    auto store_smem = [&](int st) {
        char* aP = smem + st * A_STG_B;
        char* bP = smem + B_BASE + st * B_STG_B;
        // A: 8 floats -> permuted fp16 pairs (j, j+4) -> one uint4 per task
        #pragma unroll
        for (int i = 0; i < 2; ++i) {
            const int task = i * 256 + tid;
            const int row = task >> 2, grp = task & 3;
            const float4 v0 = xr[i * 2 + 0];
            const float4 v1 = xr[i * 2 + 1];
            uint4 u;
            u.x = f22h2(v0.x, v1.x);
            u.y = f22h2(v0.y, v1.y);
            u.z = f22h2(v0.z, v1.z);
            u.w = f22h2(v0.w, v1.w);
            *reinterpret_cast<uint4*>(aP + (row * KPAD + grp * 8) * 2) = u;
        }
        // B: lop3 nibble->fp16 (1024+w), exact hsub2 of (1024+z), hmul2 by s
        const float zf = (float)(((zw >> zsh) & 0xF) + 1 + 1024);
        const __half2 z2 = __floats2half2_rn(zf, zf);
        const __half2 s2 = __floats2half2_rn(sc, sc);
        #pragma unroll
        for (int p = 0; p < 4; ++p) {
            const uint32_t q = (uint32_t)wq[p];
            uint4 u;
            uint32_t t;
            __half2 hv, r;
            t = (q & 0x000F000Fu) | 0x64006400u;
            hv = reinterpret_cast<__half2&>(t);
            r = __hmul2(__hsub2(hv, z2), s2);  u.x = reinterpret_cast<uint32_t&>(r);
            t = ((q >> 4) & 0x000F000Fu) | 0x64006400u;
            hv = reinterpret_cast<__half2&>(t);
            r = __hmul2(__hsub2(hv, z2), s2);  u.y = reinterpret_cast<uint32_t&>(r);
            t = ((q >> 8) & 0x000F000Fu) | 0x64006400u;
            hv = reinterpret_cast<__half2&>(t);
            r = __hmul2(__hsub2(hv, z2), s2);  u.z = reinterpret_cast<uint32_t&>(r);
            t = ((q >> 12) & 0x000F000Fu) | 0x64006400u;
            hv = reinterpret_cast<__half2&>(t);
            r = __hmul2(__hsub2(hv, z2), s2);  u.w = reinterpret_cast<uint32_t&>(r);
            *reinterpret_cast<uint4*>(bP + (oc * KPAD + p * 8) * 2) = u;
        }
    };

    auto compute = [&](int st) {
        const uint32_t aS = sb + st * A_STG_B;
        const uint32_t bS = sb + B_BASE + st * B_STG_B;
        #pragma unroll
        for (int ks = 0; ks < 2; ++ks) {
            uint32_t af[4][4];
            #pragma unroll
            for (int ma = 0; ma < 4; ++ma) {
                const int row = wm * 64 + ma * 16 + (lid & 15);
                const int col = ks * 16 + (lid >> 4) * 8;
                ldm_x4(af[ma][0], af[ma][1], af[ma][2], af[ma][3],
                       aS + (uint32_t)(row * KPAD + col) * 2);
            }
            uint32_t bf[8][2];
            #pragma unroll
            for (int g4 = 0; g4 < 4; ++g4) {
                const int row = wn * 64 + g4 * 16 + ((lid >> 4) & 1) * 8 + (lid & 7);
                const int col = ks * 16 + ((lid >> 3) & 1) * 8;
                uint32_t r0, r1, r2, r3;
                ldm_x4(r0, r1, r2, r3, bS + (uint32_t)(row * KPAD + col) * 2);
                bf[g4 * 2 + 0][0] = r0; bf[g4 * 2 + 0][1] = r1;
                bf[g4 * 2 + 1][0] = r2; bf[g4 * 2 + 1][1] = r3;
            }
            #pragma unroll
            for (int ma = 0; ma < 4; ++ma)
                #pragma unroll
                for (int na = 0; na < 8; ++na)
                    mma16816(acc[ma][na], af[ma], bf[na]);
        }
    };

    // ---- pipeline: prefetch next chunk into regs, compute current, store ----
    load_regs(0);
    store_smem(0);
    __syncthreads();

    for (int kt = 0; kt < NC; ++kt) {
        if (kt + 1 < NC) load_regs(kt + 1);
        compute(kt & 1);
        if (kt + 1 < NC) store_smem((kt + 1) & 1);
        __syncthreads();
    }

    // ---- epilogue ----
    #pragma unroll
    for (int ma = 0; ma < 4; ++ma) {
        const int row = m0 + wm * 64 + ma * 16 + (lid >> 2);
        #pragma unroll
        for (int na = 0; na < 8; ++na) {
            const int col = n0 + wn * 64 + na * 8 + (lid & 3) * 2;
            float2 v01, v23;
            v01.x = acc[ma][na][0]; v01.y = acc[ma][na][1];
            v23.x = acc[ma][na][2]; v23.y = acc[ma][na][3];
            *reinterpret_cast<float2*>(&out[(size_t)row * OUT_F + col]) = v01;
            *reinterpret_cast<float2*>(&out[(size_t)(row + 8) * OUT_F + col]) = v23;
        }
    }
}

extern "C" void kernel_launch(void* const* d_in, const int* in_sizes, int n_in,
                              void* d_out, int out_size)
{
    const float* x       = (const float*)d_in[0];
    const int*   qweight = (const int*)  d_in[1];
    const int*   qzeros  = (const int*)  d_in[2];
    const float* scales  = (const float*)d_in[3];
    float*       out     = (float*)d_out;

    cudaFuncSetAttribute(gptq_mma_kernel,
                         cudaFuncAttributeMaxDynamicSharedMemorySize, SMEM_TOTAL);
    dim3 grid(OUT_F / BN, MROWS / BM);   // 43 x 64
    gptq_mma_kernel<<<grid, THREADS, SMEM_TOTAL>>>(x, qweight, qzeros, scales, out);
}

// round 11
// speedup vs baseline: 1.4102x; 1.1401x over previous
#include <cuda_runtime.h>
#include <cuda_fp16.h>
#include <cstdint>

#define IN_F   4096
#define OUT_F  11008
#define GS     128
#define MROWS  8192

// x in fp16, k-permuted within each 8-group: order (j0,j4,j1,j5,j2,j6,j3,j7).
__device__ __half g_xh[(size_t)MROWS * IN_F];   // 67 MB scratch (device global)

// =============================== prepass ===================================
__global__ __launch_bounds__(256)
void conv_x_perm_kernel(const float* __restrict__ x)
{
    const size_t i = ((size_t)blockIdx.x * 256 + threadIdx.x) * 8;  // one 8-group
    const float4 a = *reinterpret_cast<const float4*>(&x[i]);
    const float4 b = *reinterpret_cast<const float4*>(&x[i + 4]);
    __half2 h0 = __floats2half2_rn(a.x, b.x);   // (j0, j4)
    __half2 h1 = __floats2half2_rn(a.y, b.y);   // (j1, j5)
    __half2 h2 = __floats2half2_rn(a.z, b.z);   // (j2, j6)
    __half2 h3 = __floats2half2_rn(a.w, b.w);   // (j3, j7)
    uint4 u;
    u.x = reinterpret_cast<uint32_t&>(h0);
    u.y = reinterpret_cast<uint32_t&>(h1);
    u.z = reinterpret_cast<uint32_t&>(h2);
    u.w = reinterpret_cast<uint32_t&>(h3);
    *reinterpret_cast<uint4*>(&g_xh[i]) = u;
}

// =============================== GEMM ======================================
constexpr int BM = 128;
constexpr int BN = 256;
constexpr int BK = 64;               // doubled: halves barrier count
constexpr int KPAD = 72;             // 144B row stride; 144/16=9 -> conflict-free ldmatrix
constexpr int THREADS = 256;
constexpr int NC = IN_F / BK;        // 64

constexpr int A_STG_B = BM * KPAD * 2;            // 18432 bytes/stage
constexpr int B_STG_B = BN * KPAD * 2;            // 36864 bytes/stage
constexpr int B_BASE  = 2 * A_STG_B;              // 36864
constexpr int SMEM_TOTAL = 2 * A_STG_B + 2 * B_STG_B;   // 110592

__device__ __forceinline__ void ldm_x4(uint32_t& r0, uint32_t& r1,
                                       uint32_t& r2, uint32_t& r3, uint32_t addr) {
    asm volatile("ldmatrix.sync.aligned.m8n8.x4.shared.b16 {%0,%1,%2,%3}, [%4];"
                 : "=r"(r0), "=r"(r1), "=r"(r2), "=r"(r3) : "r"(addr));
}

__device__ __forceinline__ void mma16816(float* d, const uint32_t* a, const uint32_t* b) {
    asm volatile("mma.sync.aligned.m16n8k16.row.col.f32.f16.f16.f32 "
                 "{%0,%1,%2,%3}, {%4,%5,%6,%7}, {%8,%9}, {%0,%1,%2,%3};"
                 : "+f"(d[0]), "+f"(d[1]), "+f"(d[2]), "+f"(d[3])
                 : "r"(a[0]), "r"(a[1]), "r"(a[2]), "r"(a[3]),
                   "r"(b[0]), "r"(b[1]));
}

__global__ __launch_bounds__(THREADS, 1)
void gptq_mma_kernel(const int*   __restrict__ qweight,
                     const int*   __restrict__ qzeros,
                     const float* __restrict__ scales,
                     float*       __restrict__ out)
{
    extern __shared__ __align__(16) char smem[];
    const uint32_t sb = (uint32_t)__cvta_generic_to_shared(smem);

    const int tid = threadIdx.x;
    const int lid = tid & 31;
    const int wid = tid >> 5;
    const int wm  = wid & 1;           // 2 warps along M (64 rows)
    const int wn  = wid >> 1;          // 4 warps along N (64 cols)
    const int m0  = blockIdx.y * BM;
    const int n0  = blockIdx.x * BN;

    const int oc   = tid;              // B producer: one output column each
    const int ncol = n0 + oc;
    const int zsh  = (oc & 7) * 4;

    uint4 xr[4];                       // A prefetch: 4 x 8 halfs
    int   wq[8];                       // B prefetch: 8 packed int32 (64 k)
    int   zw;
    float sc;

    float acc[4][8][4];
    #pragma unroll
    for (int i = 0; i < 4; ++i)
        #pragma unroll
        for (int j = 0; j < 8; ++j)
            #pragma unroll
            for (int q = 0; q < 4; ++q) acc[i][j][q] = 0.0f;

    // A: 128 rows x 8 segments of 8 halfs = 1024 tasks, 4/thread.
    auto load_regs = [&](int kt) {
        const int k0 = kt * BK;
        #pragma unroll
        for (int i = 0; i < 4; ++i) {
            const int task = i * 256 + tid;
            const int row = task >> 3, seg = task & 7;
            xr[i] = *reinterpret_cast<const uint4*>(
                &g_xh[(size_t)(m0 + row) * IN_F + k0 + seg * 8]);
        }
        const int g = kt >> 1;         // k0 / GS
        zw = qzeros[(size_t)g * (OUT_F / 8) + (ncol >> 3)];
        sc = scales[(size_t)g * OUT_F + ncol];
        #pragma unroll
        for (int p = 0; p < 8; ++p)
            wq[p] = qweight[(size_t)(k0 / 8 + p) * OUT_F + ncol];
    };

    auto store_smem = [&](int st) {
        char* aP = smem + st * A_STG_B;
        char* bP = smem + B_BASE + st * B_STG_B;
        #pragma unroll
        for (int i = 0; i < 4; ++i) {
            const int task = i * 256 + tid;
            const int row = task >> 3, seg = task & 7;
            *reinterpret_cast<uint4*>(aP + (row * KPAD + seg * 8) * 2) = xr[i];
        }
        const float zf = (float)(((zw >> zsh) & 0xF) + 1 + 1024);
        const __half2 z2 = __floats2half2_rn(zf, zf);
        const __half2 s2 = __floats2half2_rn(sc, sc);
        #pragma unroll
        for (int p = 0; p < 8; ++p) {
            const uint32_t q = (uint32_t)wq[p];
            uint4 u;
            uint32_t t;
            __half2 hv, r;
            t = (q & 0x000F000Fu) | 0x64006400u;
            hv = reinterpret_cast<__half2&>(t);
            r = __hmul2(__hsub2(hv, z2), s2);  u.x = reinterpret_cast<uint32_t&>(r);
            t = ((q >> 4) & 0x000F000Fu) | 0x64006400u;
            hv = reinterpret_cast<__half2&>(t);
            r = __hmul2(__hsub2(hv, z2), s2);  u.y = reinterpret_cast<uint32_t&>(r);
            t = ((q >> 8) & 0x000F000Fu) | 0x64006400u;
            hv = reinterpret_cast<__half2&>(t);
            r = __hmul2(__hsub2(hv, z2), s2);  u.z = reinterpret_cast<uint32_t&>(r);
            t = ((q >> 12) & 0x000F000Fu) | 0x64006400u;
            hv = reinterpret_cast<__half2&>(t);
            r = __hmul2(__hsub2(hv, z2), s2);  u.w = reinterpret_cast<uint32_t&>(r);
            *reinterpret_cast<uint4*>(bP + (oc * KPAD + p * 8) * 2) = u;
        }
    };

    auto compute = [&](int st) {
        const uint32_t aS = sb + st * A_STG_B;
        const uint32_t bS = sb + B_BASE + st * B_STG_B;
        #pragma unroll
        for (int ks = 0; ks < 4; ++ks) {
            uint32_t af[4][4];
            #pragma unroll
            for (int ma = 0; ma < 4; ++ma) {
                const int row = wm * 64 + ma * 16 + (lid & 15);
                const int col = ks * 16 + (lid >> 4) * 8;
                ldm_x4(af[ma][0], af[ma][1], af[ma][2], af[ma][3],
                       aS + (uint32_t)(row * KPAD + col) * 2);
            }
            uint32_t bf[8][2];
            #pragma unroll
            for (int g4 = 0; g4 < 4; ++g4) {
                const int row = wn * 64 + g4 * 16 + ((lid >> 4) & 1) * 8 + (lid & 7);
                const int col = ks * 16 + ((lid >> 3) & 1) * 8;
                uint32_t r0, r1, r2, r3;
                ldm_x4(r0, r1, r2, r3, bS + (uint32_t)(row * KPAD + col) * 2);
                bf[g4 * 2 + 0][0] = r0; bf[g4 * 2 + 0][1] = r1;
                bf[g4 * 2 + 1][0] = r2; bf[g4 * 2 + 1][1] = r3;
            }
            #pragma unroll
            for (int ma = 0; ma < 4; ++ma)
                #pragma unroll
                for (int na = 0; na < 8; ++na)
                    mma16816(acc[ma][na], af[ma], bf[na]);
        }
    };

    // ---- pipeline: prefetch next chunk into regs, compute current, store ----
    load_regs(0);
    store_smem(0);
    __syncthreads();

    for (int kt = 0; kt < NC; ++kt) {
        if (kt + 1 < NC) load_regs(kt + 1);
        compute(kt & 1);
        if (kt + 1 < NC) store_smem((kt + 1) & 1);
        __syncthreads();
    }

    // ---- epilogue ----
    #pragma unroll
    for (int ma = 0; ma < 4; ++ma) {
        const int row = m0 + wm * 64 + ma * 16 + (lid >> 2);
        #pragma unroll
        for (int na = 0; na < 8; ++na) {
            const int col = n0 + wn * 64 + na * 8 + (lid & 3) * 2;
            float2 v01, v23;
            v01.x = acc[ma][na][0]; v01.y = acc[ma][na][1];
            v23.x = acc[ma][na][2]; v23.y = acc[ma][na][3];
            *reinterpret_cast<float2*>(&out[(size_t)row * OUT_F + col]) = v01;
            *reinterpret_cast<float2*>(&out[(size_t)(row + 8) * OUT_F + col]) = v23;
        }
    }
}

// =============================== launch ====================================
extern "C" void kernel_launch(void* const* d_in, const int* in_sizes, int n_in,
                              void* d_out, int out_size)
{
    const float* x       = (const float*)d_in[0];
    const int*   qweight = (const int*)  d_in[1];
    const int*   qzeros  = (const int*)  d_in[2];
    const float* scales  = (const float*)d_in[3];
    float*       out     = (float*)d_out;

    cudaFuncSetAttribute(gptq_mma_kernel,
                         cudaFuncAttributeMaxDynamicSharedMemorySize, SMEM_TOTAL);

    conv_x_perm_kernel<<<(MROWS * IN_F) / (256 * 8), 256>>>(x);

    dim3 grid(OUT_F / BN, MROWS / BM);   // 43 x 64
    gptq_mma_kernel<<<grid, THREADS, SMEM_TOTAL>>>(qweight, qzeros, scales, out);
}

// round 12
// speedup vs baseline: 1.4126x; 1.0017x over previous
#include <cuda_runtime.h>
#include <cuda_fp16.h>
#include <cstdint>

#define IN_F   4096
#define OUT_F  11008
#define GS     128
#define MROWS  8192

// x in fp16, k-permuted within each 8-group: order (j0,j4,j1,j5,j2,j6,j3,j7).
__device__ __half g_xh[(size_t)MROWS * IN_F];   // 67 MB scratch (device global)

// =============================== prepass ===================================
__global__ __launch_bounds__(256)
void conv_x_perm_kernel(const float* __restrict__ x)
{
    const size_t i = ((size_t)blockIdx.x * 256 + threadIdx.x) * 8;  // one 8-group
    const float4 a = *reinterpret_cast<const float4*>(&x[i]);
    const float4 b = *reinterpret_cast<const float4*>(&x[i + 4]);
    __half2 h0 = __floats2half2_rn(a.x, b.x);   // (j0, j4)
    __half2 h1 = __floats2half2_rn(a.y, b.y);   // (j1, j5)
    __half2 h2 = __floats2half2_rn(a.z, b.z);   // (j2, j6)
    __half2 h3 = __floats2half2_rn(a.w, b.w);   // (j3, j7)
    uint4 u;
    u.x = reinterpret_cast<uint32_t&>(h0);
    u.y = reinterpret_cast<uint32_t&>(h1);
    u.z = reinterpret_cast<uint32_t&>(h2);
    u.w = reinterpret_cast<uint32_t&>(h3);
    *reinterpret_cast<uint4*>(&g_xh[i]) = u;
}

// =============================== GEMM ======================================
constexpr int BM = 128;
constexpr int BN = 256;
constexpr int BK = 64;
constexpr int KPAD = 72;             // 144B row stride; odd quad count -> conflict-free
constexpr int THREADS = 320;         // 8 consumer warps + 2 producer warps
constexpr int NC = IN_F / BK;        // 64
constexpr int STAGES = 3;

constexpr int A_STG_B = BM * KPAD * 2;            // 18432
constexpr int B_STG_B = BN * KPAD * 2;            // 36864
constexpr int ST_B    = A_STG_B + B_STG_B;        // 55296
constexpr int STAGE_BASE = 1024;
constexpr int SMEM_TOTAL = STAGE_BASE + STAGES * ST_B;   // 166912

__device__ __forceinline__ void mbar_init(uint32_t a, uint32_t cnt) {
    asm volatile("mbarrier.init.shared.b64 [%0], %1;" :: "r"(a), "r"(cnt) : "memory");
}
__device__ __forceinline__ void mbar_arrive(uint32_t a) {
    asm volatile("mbarrier.arrive.shared.b64 _, [%0];" :: "r"(a) : "memory");
}
__device__ __forceinline__ void mbar_wait(uint32_t a, uint32_t parity) {
    uint32_t done;
    asm volatile("{\n\t.reg .pred p;\n\t"
                 "mbarrier.try_wait.parity.acquire.cta.shared::cta.b64 p, [%1], %2;\n\t"
                 "selp.b32 %0, 1, 0, p;\n\t}"
                 : "=r"(done) : "r"(a), "r"(parity) : "memory");
    if (!done) {
        asm volatile("{\n\t.reg .pred P1;\n\t"
                     "WL_%=:\n\t"
                     "mbarrier.try_wait.parity.acquire.cta.shared::cta.b64 P1, [%0], %1, 0x989680;\n\t"
                     "@P1 bra.uni WD_%=;\n\t"
                     "bra.uni WL_%=;\n\t"
                     "WD_%=:\n\t}"
                     :: "r"(a), "r"(parity) : "memory");
    }
}

__device__ __forceinline__ void ldm_x4(uint32_t& r0, uint32_t& r1,
                                       uint32_t& r2, uint32_t& r3, uint32_t addr) {
    asm volatile("ldmatrix.sync.aligned.m8n8.x4.shared.b16 {%0,%1,%2,%3}, [%4];"
                 : "=r"(r0), "=r"(r1), "=r"(r2), "=r"(r3) : "r"(addr));
}

__device__ __forceinline__ void mma16816(float* d, const uint32_t* a, const uint32_t* b) {
    asm volatile("mma.sync.aligned.m16n8k16.row.col.f32.f16.f16.f32 "
                 "{%0,%1,%2,%3}, {%4,%5,%6,%7}, {%8,%9}, {%0,%1,%2,%3};"
                 : "+f"(d[0]), "+f"(d[1]), "+f"(d[2]), "+f"(d[3])
                 : "r"(a[0]), "r"(a[1]), "r"(a[2]), "r"(a[3]),
                   "r"(b[0]), "r"(b[1]));
}

__global__ __launch_bounds__(THREADS, 1)
void gptq_mma_kernel(const int*   __restrict__ qweight,
                     const int*   __restrict__ qzeros,
                     const float* __restrict__ scales,
                     float*       __restrict__ out)
{
    extern __shared__ __align__(16) char smem[];
    const uint32_t sb = (uint32_t)__cvta_generic_to_shared(smem);

    const int tid = threadIdx.x;
    const int lid = tid & 31;
    const int wid = tid >> 5;
    const int m0  = blockIdx.y * BM;
    const int n0  = blockIdx.x * BN;

    // mbarriers: full[s] at sb + s*16, empty[s] at sb + s*16 + 8
    if (tid == 0) {
        #pragma unroll
        for (int s = 0; s < STAGES; ++s) {
            mbar_init(sb + s * 16,     64);    // full: producer threads
            mbar_init(sb + s * 16 + 8, 256);   // empty: consumer threads
        }
    }
    __syncthreads();

    if (wid < 8) {
        // ====================== CONSUMER ======================
        const int wm = wid & 1;        // 2 warps along M (64 rows)
        const int wn = wid >> 1;       // 4 warps along N (64 cols)

        float acc[4][8][4];
        #pragma unroll
        for (int i = 0; i < 4; ++i)
            #pragma unroll
            for (int j = 0; j < 8; ++j)
                #pragma unroll
                for (int q = 0; q < 4; ++q) acc[i][j][q] = 0.0f;

        int st = 0, ph = 0;
        for (int kt = 0; kt < NC; ++kt) {
            mbar_wait(sb + st * 16, ph);                 // full[st]

            const uint32_t aS = sb + STAGE_BASE + st * ST_B;
            const uint32_t bS = aS + A_STG_B;
            #pragma unroll
            for (int ks = 0; ks < 4; ++ks) {
                uint32_t af[4][4];
                #pragma unroll
                for (int ma = 0; ma < 4; ++ma) {
                    const int row = wm * 64 + ma * 16 + (lid & 15);
                    const int col = ks * 16 + (lid >> 4) * 8;
                    ldm_x4(af[ma][0], af[ma][1], af[ma][2], af[ma][3],
                           aS + (uint32_t)(row * KPAD + col) * 2);
                }
                uint32_t bf[8][2];
                #pragma unroll
                for (int g4 = 0; g4 < 4; ++g4) {
                    const int row = wn * 64 + g4 * 16 + ((lid >> 4) & 1) * 8 + (lid & 7);
                    const int col = ks * 16 + ((lid >> 3) & 1) * 8;
                    uint32_t r0, r1, r2, r3;
                    ldm_x4(r0, r1, r2, r3, bS + (uint32_t)(row * KPAD + col) * 2);
                    bf[g4 * 2 + 0][0] = r0; bf[g4 * 2 + 0][1] = r1;
                    bf[g4 * 2 + 1][0] = r2; bf[g4 * 2 + 1][1] = r3;
                }
                #pragma unroll
                for (int ma = 0; ma < 4; ++ma)
                    #pragma unroll
                    for (int na = 0; na < 8; ++na)
                        mma16816(acc[ma][na], af[ma], bf[na]);
            }

            mbar_arrive(sb + st * 16 + 8);               // empty[st]
            if (++st == STAGES) { st = 0; ph ^= 1; }
        }

        // ---- epilogue ----
        #pragma unroll
        for (int ma = 0; ma < 4; ++ma) {
            const int row = m0 + wm * 64 + ma * 16 + (lid >> 2);
            #pragma unroll
            for (int na = 0; na < 8; ++na) {
                const int col = n0 + wn * 64 + na * 8 + (lid & 3) * 2;
                float2 v01, v23;
                v01.x = acc[ma][na][0]; v01.y = acc[ma][na][1];
                v23.x = acc[ma][na][2]; v23.y = acc[ma][na][3];
                *reinterpret_cast<float2*>(&out[(size_t)row * OUT_F + col]) = v01;
                *reinterpret_cast<float2*>(&out[(size_t)(row + 8) * OUT_F + col]) = v23;
            }
        }
    } else {
        // ====================== PRODUCER (warps 8-9) ======================
        const int ptid = tid - 256;    // 0..63
        const int zsh  = (ptid & 7) * 4;

        int st = 0, ph = 1;            // empty-wait passes for the first STAGES chunks
        for (int kt = 0; kt < NC; ++kt) {
            const int k0 = kt * BK;
            const int g  = kt >> 1;    // k0 / GS

            // ---- prefetch W / zeros / scales into regs (before the wait) ----
            int   wq[4][8];
            int   zv[4];
            float sv[4];
            #pragma unroll
            for (int c = 0; c < 4; ++c) {
                const int ncol = n0 + ptid + 64 * c;
                zv[c] = qzeros[(size_t)g * (OUT_F / 8) + (ncol >> 3)];
                sv[c] = scales[(size_t)g * OUT_F + ncol];
                #pragma unroll
                for (int p = 0; p < 8; ++p)
                    wq[c][p] = qweight[(size_t)(k0 / 8 + p) * OUT_F + ncol];
            }

            mbar_wait(sb + st * 16 + 8, ph);             // empty[st]

            char* aP = smem + STAGE_BASE + st * ST_B;
            char* bP = aP + A_STG_B;

            // ---- B: dequant 4 cols x 8 packed rows ----
            #pragma unroll
            for (int c = 0; c < 4; ++c) {
                const float zf = (float)(((zv[c] >> zsh) & 0xF) + 1 + 1024);
                const __half2 z2 = __floats2half2_rn(zf, zf);
                const __half2 s2 = __floats2half2_rn(sv[c], sv[c]);
                const int colo = ptid + 64 * c;
                #pragma unroll
                for (int p = 0; p < 8; ++p) {
                    const uint32_t q = (uint32_t)wq[c][p];
                    uint4 u;
                    uint32_t t;
                    __half2 hv, r;
                    t = (q & 0x000F000Fu) | 0x64006400u;
                    hv = reinterpret_cast<__half2&>(t);
                    r = __hmul2(__hsub2(hv, z2), s2);  u.x = reinterpret_cast<uint32_t&>(r);
                    t = ((q >> 4) & 0x000F000Fu) | 0x64006400u;
                    hv = reinterpret_cast<__half2&>(t);
                    r = __hmul2(__hsub2(hv, z2), s2);  u.y = reinterpret_cast<uint32_t&>(r);
                    t = ((q >> 8) & 0x000F000Fu) | 0x64006400u;
                    hv = reinterpret_cast<__half2&>(t);
                    r = __hmul2(__hsub2(hv, z2), s2);  u.z = reinterpret_cast<uint32_t&>(r);
                    t = ((q >> 12) & 0x000F000Fu) | 0x64006400u;
                    hv = reinterpret_cast<__half2&>(t);
                    r = __hmul2(__hsub2(hv, z2), s2);  u.w = reinterpret_cast<uint32_t&>(r);
                    *reinterpret_cast<uint4*>(bP + (colo * KPAD + p * 8) * 2) = u;
                }
            }

            // ---- A: copy 128 rows x 64 halfs (two batches of 8 uint4/thread) ----
            #pragma unroll
            for (int h = 0; h < 2; ++h) {
                uint4 v[8];
                #pragma unroll
                for (int i = 0; i < 8; ++i) {
                    const int task = (h * 8 + i) * 64 + ptid;
                    const int row = task >> 3, seg = task & 7;
                    v[i] = *reinterpret_cast<const uint4*>(
                        &g_xh[(size_t)(m0 + row) * IN_F + k0 + seg * 8]);
                }
                #pragma unroll
                for (int i = 0; i < 8; ++i) {
                    const int task = (h * 8 + i) * 64 + ptid;
                    const int row = task >> 3, seg = task & 7;
                    *reinterpret_cast<uint4*>(aP + (row * KPAD + seg * 8) * 2) = v[i];
                }
            }

            mbar_arrive(sb + st * 16);                   // full[st]
            if (++st == STAGES) { st = 0; ph ^= 1; }
        }
    }
}

// =============================== launch ====================================
extern "C" void kernel_launch(void* const* d_in, const int* in_sizes, int n_in,
                              void* d_out, int out_size)
{
    const float* x       = (const float*)d_in[0];
    const int*   qweight = (const int*)  d_in[1];
    const int*   qzeros  = (const int*)  d_in[2];
    const float* scales  = (const float*)d_in[3];
    float*       out     = (float*)d_out;

    cudaFuncSetAttribute(gptq_mma_kernel,
                         cudaFuncAttributeMaxDynamicSharedMemorySize, SMEM_TOTAL);

    conv_x_perm_kernel<<<(MROWS * IN_F) / (256 * 8), 256>>>(x);

    dim3 grid(OUT_F / BN, MROWS / BM);   // 43 x 64
    gptq_mma_kernel<<<grid, THREADS, SMEM_TOTAL>>>(qweight, qzeros, scales, out);
}

// round 13
// speedup vs baseline: 1.4915x; 1.0558x over previous
#include <cuda_runtime.h>
#include <cuda_fp16.h>
#include <cstdint>

#define IN_F   4096
#define OUT_F  11008
#define GS     128
#define MROWS  8192

// x in fp16, k-permuted within each 8-group: order (j0,j4,j1,j5,j2,j6,j3,j7).
__device__ __half g_xh[(size_t)MROWS * IN_F];   // 67 MB scratch (device global)

// =============================== prepass ===================================
__global__ __launch_bounds__(256)
void conv_x_perm_kernel(const float* __restrict__ x)
{
    const size_t i = ((size_t)blockIdx.x * 256 + threadIdx.x) * 8;  // one 8-group
    const float4 a = *reinterpret_cast<const float4*>(&x[i]);
    const float4 b = *reinterpret_cast<const float4*>(&x[i + 4]);
    __half2 h0 = __floats2half2_rn(a.x, b.x);   // (j0, j4)
    __half2 h1 = __floats2half2_rn(a.y, b.y);   // (j1, j5)
    __half2 h2 = __floats2half2_rn(a.z, b.z);   // (j2, j6)
    __half2 h3 = __floats2half2_rn(a.w, b.w);   // (j3, j7)
    uint4 u;
    u.x = reinterpret_cast<uint32_t&>(h0);
    u.y = reinterpret_cast<uint32_t&>(h1);
    u.z = reinterpret_cast<uint32_t&>(h2);
    u.w = reinterpret_cast<uint32_t&>(h3);
    *reinterpret_cast<uint4*>(&g_xh[i]) = u;
}

// =============================== GEMM ======================================
constexpr int BM = 128;
constexpr int BN = 256;
constexpr int BK = 64;
constexpr int KPAD = 72;             // 144B row stride; odd quad count -> conflict-free
constexpr int THREADS = 384;         // 8 consumer warps + 4 producer warps
constexpr int NC = IN_F / BK;        // 64
constexpr int STAGES = 3;

constexpr int A_STG_B = BM * KPAD * 2;            // 18432
constexpr int B_STG_B = BN * KPAD * 2;            // 36864
constexpr int ST_B    = A_STG_B + B_STG_B;        // 55296
constexpr int STAGE_BASE = 1024;
constexpr int SMEM_TOTAL = STAGE_BASE + STAGES * ST_B;   // 166912

__device__ __forceinline__ void mbar_init(uint32_t a, uint32_t cnt) {
    asm volatile("mbarrier.init.shared.b64 [%0], %1;" :: "r"(a), "r"(cnt) : "memory");
}
__device__ __forceinline__ void mbar_arrive(uint32_t a) {
    asm volatile("mbarrier.arrive.shared.b64 _, [%0];" :: "r"(a) : "memory");
}
__device__ __forceinline__ void mbar_wait(uint32_t a, uint32_t parity) {
    uint32_t done;
    asm volatile("{\n\t.reg .pred p;\n\t"
                 "mbarrier.try_wait.parity.acquire.cta.shared::cta.b64 p, [%1], %2;\n\t"
                 "selp.b32 %0, 1, 0, p;\n\t}"
                 : "=r"(done) : "r"(a), "r"(parity) : "memory");
    if (!done) {
        asm volatile("{\n\t.reg .pred P1;\n\t"
                     "WL_%=:\n\t"
                     "mbarrier.try_wait.parity.acquire.cta.shared::cta.b64 P1, [%0], %1, 0x989680;\n\t"
                     "@P1 bra.uni WD_%=;\n\t"
                     "bra.uni WL_%=;\n\t"
                     "WD_%=:\n\t}"
                     :: "r"(a), "r"(parity) : "memory");
    }
}

__device__ __forceinline__ void ldm_x4(uint32_t& r0, uint32_t& r1,
                                       uint32_t& r2, uint32_t& r3, uint32_t addr) {
    asm volatile("ldmatrix.sync.aligned.m8n8.x4.shared.b16 {%0,%1,%2,%3}, [%4];"
                 : "=r"(r0), "=r"(r1), "=r"(r2), "=r"(r3) : "r"(addr));
}

__device__ __forceinline__ void mma16816(float* d, const uint32_t* a, const uint32_t* b) {
    asm volatile("mma.sync.aligned.m16n8k16.row.col.f32.f16.f16.f32 "
                 "{%0,%1,%2,%3}, {%4,%5,%6,%7}, {%8,%9}, {%0,%1,%2,%3};"
                 : "+f"(d[0]), "+f"(d[1]), "+f"(d[2]), "+f"(d[3])
                 : "r"(a[0]), "r"(a[1]), "r"(a[2]), "r"(a[3]),
                   "r"(b[0]), "r"(b[1]));
}

__global__ __launch_bounds__(THREADS, 1)
void gptq_mma_kernel(const int*   __restrict__ qweight,
                     const int*   __restrict__ qzeros,
                     const float* __restrict__ scales,
                     float*       __restrict__ out)
{
    extern __shared__ __align__(16) char smem[];
    const uint32_t sb = (uint32_t)__cvta_generic_to_shared(smem);

    const int tid = threadIdx.x;
    const int lid = tid & 31;
    const int wid = tid >> 5;
    const int m0  = blockIdx.y * BM;
    const int n0  = blockIdx.x * BN;

    // mbarriers: full[s] at sb + s*16, empty[s] at sb + s*16 + 8
    if (tid == 0) {
        #pragma unroll
        for (int s = 0; s < STAGES; ++s) {
            mbar_init(sb + s * 16,     128);   // full: producer threads
            mbar_init(sb + s * 16 + 8, 256);   // empty: consumer threads
        }
    }
    __syncthreads();

    if (wid < 8) {
        // ====================== CONSUMER ======================
        const int wm = wid & 1;        // 2 warps along M (64 rows)
        const int wn = wid >> 1;       // 4 warps along N (64 cols)

        float acc[4][8][4];
        #pragma unroll
        for (int i = 0; i < 4; ++i)
            #pragma unroll
            for (int j = 0; j < 8; ++j)
                #pragma unroll
                for (int q = 0; q < 4; ++q) acc[i][j][q] = 0.0f;

        int st = 0, ph = 0;
        for (int kt = 0; kt < NC; ++kt) {
            mbar_wait(sb + st * 16, ph);                 // full[st]

            const uint32_t aS = sb + STAGE_BASE + st * ST_B;
            const uint32_t bS = aS + A_STG_B;
            #pragma unroll
            for (int ks = 0; ks < 4; ++ks) {
                uint32_t af[4][4];
                #pragma unroll
                for (int ma = 0; ma < 4; ++ma) {
                    const int row = wm * 64 + ma * 16 + (lid & 15);
                    const int col = ks * 16 + (lid >> 4) * 8;
                    ldm_x4(af[ma][0], af[ma][1], af[ma][2], af[ma][3],
                           aS + (uint32_t)(row * KPAD + col) * 2);
                }
                uint32_t bf[8][2];
                #pragma unroll
                for (int g4 = 0; g4 < 4; ++g4) {
                    const int row = wn * 64 + g4 * 16 + ((lid >> 4) & 1) * 8 + (lid & 7);
                    const int col = ks * 16 + ((lid >> 3) & 1) * 8;
                    uint32_t r0, r1, r2, r3;
                    ldm_x4(r0, r1, r2, r3, bS + (uint32_t)(row * KPAD + col) * 2);
                    bf[g4 * 2 + 0][0] = r0; bf[g4 * 2 + 0][1] = r1;
                    bf[g4 * 2 + 1][0] = r2; bf[g4 * 2 + 1][1] = r3;
                }
                // all smem reads for this stage are done after the last ldm:
                // release the stage before the final mma block.
                if (ks == 3) mbar_arrive(sb + st * 16 + 8);   // empty[st]
                #pragma unroll
                for (int ma = 0; ma < 4; ++ma)
                    #pragma unroll
                    for (int na = 0; na < 8; ++na)
                        mma16816(acc[ma][na], af[ma], bf[na]);
            }

            if (++st == STAGES) { st = 0; ph ^= 1; }
        }

        // ---- epilogue ----
        #pragma unroll
        for (int ma = 0; ma < 4; ++ma) {
            const int row = m0 + wm * 64 + ma * 16 + (lid >> 2);
            #pragma unroll
            for (int na = 0; na < 8; ++na) {
                const int col = n0 + wn * 64 + na * 8 + (lid & 3) * 2;
                float2 v01, v23;
                v01.x = acc[ma][na][0]; v01.y = acc[ma][na][1];
                v23.x = acc[ma][na][2]; v23.y = acc[ma][na][3];
                *reinterpret_cast<float2*>(&out[(size_t)row * OUT_F + col]) = v01;
                *reinterpret_cast<float2*>(&out[(size_t)(row + 8) * OUT_F + col]) = v23;
            }
        }
    } else {
        // ====================== PRODUCER (warps 8-11) ======================
        const int ptid = tid - 256;    // 0..127
        const int zsh  = (ptid & 7) * 4;

        // double-buffered prefetch registers (literal indices after unroll)
        uint4 xr[2][8];
        int   wq[2][2][8];
        int   zv[2][2];
        float sv[2][2];

        auto loadP = [&](int kt, int buf) {
            const int k0 = kt * BK;
            const int g  = kt >> 1;    // k0 / GS
            #pragma unroll
            for (int i = 0; i < 8; ++i) {
                const int task = i * 128 + ptid;
                const int row = task >> 3, seg = task & 7;
                xr[buf][i] = *reinterpret_cast<const uint4*>(
                    &g_xh[(size_t)(m0 + row) * IN_F + k0 + seg * 8]);
            }
            #pragma unroll
            for (int c = 0; c < 2; ++c) {
                const int ncol = n0 + ptid + 128 * c;
                zv[buf][c] = qzeros[(size_t)g * (OUT_F / 8) + (ncol >> 3)];
                sv[buf][c] = scales[(size_t)g * OUT_F + ncol];
                #pragma unroll
                for (int p = 0; p < 8; ++p)
                    wq[buf][c][p] = qweight[(size_t)(k0 / 8 + p) * OUT_F + ncol];
            }
        };

        auto storeP = [&](int st, int buf) {
            char* aP = smem + STAGE_BASE + st * ST_B;
            char* bP = aP + A_STG_B;
            #pragma unroll
            for (int i = 0; i < 8; ++i) {
                const int task = i * 128 + ptid;
                const int row = task >> 3, seg = task & 7;
                *reinterpret_cast<uint4*>(aP + (row * KPAD + seg * 8) * 2) = xr[buf][i];
            }
            #pragma unroll
            for (int c = 0; c < 2; ++c) {
                const float zf = (float)(((zv[buf][c] >> zsh) & 0xF) + 1 + 1024);
                const __half2 z2 = __floats2half2_rn(zf, zf);
                const __half2 s2 = __floats2half2_rn(sv[buf][c], sv[buf][c]);
                const int colo = ptid + 128 * c;
                #pragma unroll
                for (int p = 0; p < 8; ++p) {
                    const uint32_t q = (uint32_t)wq[buf][c][p];
                    uint4 u;
                    uint32_t t;
                    __half2 hv, r;
                    t = (q & 0x000F000Fu) | 0x64006400u;
                    hv = reinterpret_cast<__half2&>(t);
                    r = __hmul2(__hsub2(hv, z2), s2);  u.x = reinterpret_cast<uint32_t&>(r);
                    t = ((q >> 4) & 0x000F000Fu) | 0x64006400u;
                    hv = reinterpret_cast<__half2&>(t);
                    r = __hmul2(__hsub2(hv, z2), s2);  u.y = reinterpret_cast<uint32_t&>(r);
                    t = ((q >> 8) & 0x000F000Fu) | 0x64006400u;
                    hv = reinterpret_cast<__half2&>(t);
                    r = __hmul2(__hsub2(hv, z2), s2);  u.z = reinterpret_cast<uint32_t&>(r);
                    t = ((q >> 12) & 0x000F000Fu) | 0x64006400u;
                    hv = reinterpret_cast<__half2&>(t);
                    r = __hmul2(__hsub2(hv, z2), s2);  u.w = reinterpret_cast<uint32_t&>(r);
                    *reinterpret_cast<uint4*>(bP + (colo * KPAD + p * 8) * 2) = u;
                }
            }
        };

        loadP(0, 0);
        int st = 0, ph = 1;            // empty-wait passes for the first STAGES chunks

        #pragma unroll 1
        for (int kt = 0; kt < NC; kt += 2) {
            // even chunk: store buf0, prefetch kt+1 into buf1 first
            if (kt + 1 < NC) loadP(kt + 1, 1);
            mbar_wait(sb + st * 16 + 8, ph);             // empty[st]
            storeP(st, 0);
            mbar_arrive(sb + st * 16);                   // full[st]
            if (++st == STAGES) { st = 0; ph ^= 1; }

            // odd chunk: store buf1, prefetch kt+2 into buf0 first
            if (kt + 2 < NC) loadP(kt + 2, 0);
            mbar_wait(sb + st * 16 + 8, ph);             // empty[st]
            storeP(st, 1);
            mbar_arrive(sb + st * 16);                   // full[st]
            if (++st == STAGES) { st = 0; ph ^= 1; }
        }
    }
}

// =============================== launch ====================================
extern "C" void kernel_launch(void* const* d_in, const int* in_sizes, int n_in,
                              void* d_out, int out_size)
{
    const float* x       = (const float*)d_in[0];
    const int*   qweight = (const int*)  d_in[1];
    const int*   qzeros  = (const int*)  d_in[2];
    const float* scales  = (const float*)d_in[3];
    float*       out     = (float*)d_out;

    cudaFuncSetAttribute(gptq_mma_kernel,
                         cudaFuncAttributeMaxDynamicSharedMemorySize, SMEM_TOTAL);

    conv_x_perm_kernel<<<(MROWS * IN_F) / (256 * 8), 256>>>(x);

    dim3 grid(OUT_F / BN, MROWS / BM);   // 43 x 64
    gptq_mma_kernel<<<grid, THREADS, SMEM_TOTAL>>>(qweight, qzeros, scales, out);
}